// round 9
// baseline (speedup 1.0000x reference)
#include <cuda_runtime.h>
#include <cuda_bf16.h>

#define NNODES 50000
#define FIN    128
#define DDIM   64
#define HDIM   128
#define BGRAPH 16
#define E1N    800000
#define E2N    200000
#define AREG   2000
#define SLOTS  2048
#define BMWORDS 1568

typedef unsigned long long ull;
typedef unsigned int u32;

// ---------------- f32x2 / bf16 helpers ------------------------------------------
__device__ __forceinline__ ull ffma2(ull a, ull b, ull c) {
    ull d;
    asm("fma.rn.f32x2 %0, %1, %2, %3;" : "=l"(d) : "l"(a), "l"(b), "l"(c));
    return d;
}
__device__ __forceinline__ ull pack2(float lo, float hi) {
    ull r;
    asm("mov.b64 %0, {%1, %2};" : "=l"(r) : "f"(lo), "f"(hi));
    return r;
}
__device__ __forceinline__ void unpack2(ull v, float& lo, float& hi) {
    asm("mov.b64 {%0, %1}, %2;" : "=f"(lo), "=f"(hi) : "l"(v));
}
__device__ __forceinline__ u32 bf2_hi(float a, float b) {
    __nv_bfloat162 h = __floats2bfloat162_rn(a, b);
    return *reinterpret_cast<u32*>(&h);
}
__device__ __forceinline__ u32 bf2_lo(float a, float b) {
    float ra = a - __bfloat162float(__float2bfloat16(a));
    float rb = b - __bfloat162float(__float2bfloat16(b));
    __nv_bfloat162 l = __floats2bfloat162_rn(ra, rb);
    return *reinterpret_cast<u32*>(&l);
}
__device__ __forceinline__ void mma16816(float* c, u32 a0, u32 a1, u32 a2, u32 a3,
                                         u32 b0, u32 b1) {
    asm("mma.sync.aligned.m16n8k16.row.col.f32.bf16.bf16.f32 "
        "{%0,%1,%2,%3}, {%4,%5,%6,%7}, {%8,%9}, {%0,%1,%2,%3};"
        : "+f"(c[0]), "+f"(c[1]), "+f"(c[2]), "+f"(c[3])
        : "r"(a0), "r"(a1), "r"(a2), "r"(a3), "r"(b0), "r"(b1));
}

// ---------------- scratch -------------------------------------------------------
__device__ __align__(16) float d_yl[NNODES * DDIM];
__device__ __align__(16) float d_yr[NNODES * DDIM];
__device__ __align__(16) float d_agg1[NNODES * DDIM];
__device__ __align__(16) float d_deg1[NNODES];
__device__ __align__(16) float d_gl[NNODES * DDIM];
__device__ __align__(16) float d_gr[NNODES * DDIM];
__device__ __align__(16) int   d_slotmap[BGRAPH * NNODES];
__device__ __align__(16) unsigned d_bitmap[BGRAPH * BMWORDS];
__device__ __align__(16) int   d_counter[BGRAPH];
__device__ __align__(16) float d_acc2[BGRAPH * SLOTS * DDIM];
__device__ __align__(16) float d_deg2[BGRAPH * SLOTS];
__device__ __align__(16) float d_u[BGRAPH * HDIM];
__device__ __align__(16) float d_c[BGRAPH];

// ---------------- clear kernel --------------------------------------------------
static constexpr int CLR_AGG1 = NNODES * DDIM / 4;
static constexpr int CLR_ACC2 = BGRAPH * SLOTS * DDIM / 4;
static constexpr int CLR_SMAP = BGRAPH * NNODES / 4;
static constexpr int CLR_BMAP = BGRAPH * BMWORDS / 4;
static constexpr int CLR_DEG1 = NNODES / 4;
static constexpr int CLR_DEG2 = BGRAPH * SLOTS / 4;
static constexpr int CLR_CNT  = BGRAPH / 4;
static constexpr int CLR_TOTAL = CLR_AGG1 + CLR_ACC2 + CLR_SMAP + CLR_BMAP +
                                 CLR_DEG1 + CLR_DEG2 + CLR_CNT;

__global__ void clear_kernel() {
    int i = blockIdx.x * blockDim.x + threadIdx.x;
    float4 z = make_float4(0.f, 0.f, 0.f, 0.f);
    if (i < CLR_AGG1) { ((float4*)d_agg1)[i] = z; return; }
    i -= CLR_AGG1;
    if (i < CLR_ACC2) { ((float4*)d_acc2)[i] = z; return; }
    i -= CLR_ACC2;
    if (i < CLR_SMAP) { ((int4*)d_slotmap)[i] = make_int4(-1, -1, -1, -1); return; }
    i -= CLR_SMAP;
    if (i < CLR_BMAP) { ((uint4*)d_bitmap)[i] = make_uint4(0, 0, 0, 0); return; }
    i -= CLR_BMAP;
    if (i < CLR_DEG1) { ((float4*)d_deg1)[i] = z; return; }
    i -= CLR_DEG1;
    if (i < CLR_DEG2) { ((float4*)d_deg2)[i] = z; return; }
    i -= CLR_DEG2;
    if (i < CLR_CNT)  { ((int4*)d_counter)[i] = make_int4(0, 0, 0, 0); }
}

// ================= HMMA bf16-split dual GEMM (64-row CTA) ========================
// Per CTA: D[64, 128] = A[64, K] @ [W1 | W2]; cols 0..63 -> C1, 64..127 -> C2+bias.
// 8 warps as 4 (rows) x 2 (col halves): warp = 16 rows x 64 cols, acc = 32 regs.
// bf16 split: D = Ah·Bh + Al·Bh + Ah·Bl (ll dropped, ~1.5e-5 rel).
// Pair-permuted smem, row stride 48 bf16 -> LDS.64 conflict-free.
template <int K, bool FUSE_H1>
__global__ __launch_bounds__(256) void mma_dual_gemm(const float* __restrict__ A,
                                                     const float* __restrict__ W1,
                                                     const float* __restrict__ W2,
                                                     const float* __restrict__ bias,
                                                     float* __restrict__ C1,
                                                     float* __restrict__ C2,
                                                     int nrows) {
    __shared__ __align__(16) __nv_bfloat16 sAh[64 * 48];
    __shared__ __align__(16) __nv_bfloat16 sAl[64 * 48];
    __shared__ __align__(16) __nv_bfloat16 sBh[128 * 48];
    __shared__ __align__(16) __nv_bfloat16 sBl[128 * 48];

    const int t = threadIdx.x;
    const int w = t >> 5, lane = t & 31;
    const int wr = w & 3, wc = w >> 2;          // row tile 0..3, col half 0..1
    const int g = lane >> 2, tg = lane & 3;
    const int row0 = blockIdx.x * 64;

    float acc[8][4];
#pragma unroll
    for (int nt = 0; nt < 8; nt++)
#pragma unroll
        for (int i = 0; i < 4; i++) acc[nt][i] = 0.f;

    for (int k0 = 0; k0 < K; k0 += 32) {
        // ---- fill A chunk (64 rows x 32 k), hi+lo; 4 pairs per thread ----
        {
            int r = t >> 2, sub = t & 3;
            int row = row0 + r;
            float inv = 1.f;
            if (FUSE_H1 && row < nrows) inv = 1.f / fmaxf(d_deg1[row], 1.f);
#pragma unroll
            for (int j = 0; j < 4; j++) {
                int jg = sub * 4 + j;
                int k = 2 * jg;
                float2 v = make_float2(0.f, 0.f);
                if (row < nrows) {
                    if (FUSE_H1) {
                        float2 ag = *(const float2*)(d_agg1 + row * 64 + k0 + k);
                        float2 yv = *(const float2*)(d_yr + row * 64 + k0 + k);
                        v.x = fmaxf(ag.x * inv + yv.x, 0.f);
                        v.y = fmaxf(ag.y * inv + yv.y, 0.f);
                    } else {
                        v = *(const float2*)(A + (long)row * K + k0 + k);
                    }
                }
                int pp = ((jg >> 2) & 1) + (jg & 3) * 2 + (jg >> 3) * 8;
                ((u32*)(sAh + r * 48))[pp] = bf2_hi(v.x, v.y);
                ((u32*)(sAl + r * 48))[pp] = bf2_lo(v.x, v.y);
            }
        }
        // ---- fill B chunk: n 0..127 = [W1 col | W2 col]; 8 pairs per thread ----
        {
            int n = t >> 1, half = t & 1;
            const float* W = (n < 64) ? W1 : W2;
            int nc = (n < 64) ? n : n - 64;
#pragma unroll
            for (int j = 0; j < 8; j++) {
                int jg = half * 8 + j;
                int k = k0 + 2 * jg;
                float wx = W[k * 64 + nc];
                float wy = W[(k + 1) * 64 + nc];
                int pp = ((jg >> 2) & 1) + (jg & 3) * 2 + (jg >> 3) * 8;
                ((u32*)(sBh + n * 48))[pp] = bf2_hi(wx, wy);
                ((u32*)(sBl + n * 48))[pp] = bf2_lo(wx, wy);
            }
        }
        __syncthreads();

        // ---- 3 split terms x 2 k16 steps x 8 n-tiles ----
#pragma unroll
        for (int term = 0; term < 3; term++) {
            const __nv_bfloat16* As = (term == 1) ? sAl : sAh;
            const __nv_bfloat16* Bs = (term == 2) ? sBl : sBh;
#pragma unroll
            for (int ks = 0; ks < 2; ks++) {
                ull av0 = *(const ull*)(As + (wr * 16 + g) * 48 + ks * 16 + tg * 4);
                ull av1 = *(const ull*)(As + (wr * 16 + g + 8) * 48 + ks * 16 + tg * 4);
                u32 a0 = (u32)av0, a2 = (u32)(av0 >> 32);
                u32 a1 = (u32)av1, a3 = (u32)(av1 >> 32);
#pragma unroll
                for (int nt = 0; nt < 8; nt++) {
                    ull bv = *(const ull*)(Bs + (wc * 64 + nt * 8 + g) * 48 + ks * 16 + tg * 4);
                    mma16816(acc[nt], a0, a1, a2, a3, (u32)bv, (u32)(bv >> 32));
                }
            }
        }
        __syncthreads();
    }

    // ---- store: warp covers rows wr*16+{g, g+8}, cols wc*64 + nt*8 + tg*2 ----
    int r0 = row0 + wr * 16 + g;
#pragma unroll
    for (int nt = 0; nt < 8; nt++) {
        int col = wc * 64 + nt * 8 + tg * 2;
        if (col < 64) {
            if (r0 < nrows)
                *(float2*)(C1 + (long)r0 * 64 + col) = make_float2(acc[nt][0], acc[nt][1]);
            if (r0 + 8 < nrows)
                *(float2*)(C1 + (long)(r0 + 8) * 64 + col) = make_float2(acc[nt][2], acc[nt][3]);
        } else {
            int c2 = col - 64;
            float2 bb = *(const float2*)(bias + c2);
            if (r0 < nrows)
                *(float2*)(C2 + (long)r0 * 64 + c2) =
                    make_float2(acc[nt][0] + bb.x, acc[nt][1] + bb.y);
            if (r0 + 8 < nrows)
                *(float2*)(C2 + (long)(r0 + 8) * 64 + c2) =
                    make_float2(acc[nt][2] + bb.x, acc[nt][3] + bb.y);
        }
    }
}

// ---------------- conv1 edge scatter (8 edges/warp) -----------------------------
__global__ void scatter1_kernel(const int* __restrict__ ei) {
    int tid = blockIdx.x * blockDim.x + threadIdx.x;
    int w = tid >> 5, lane = tid & 31;
    int e0 = 8 * w + (lane >> 4);
    int j = lane & 15;

    int s0 = ei[e0];
    int s1 = ei[e0 + 2];
    int s2 = ei[e0 + 4];
    int s3 = ei[e0 + 6];
    int dd0 = ei[E1N + e0];
    int dd1 = ei[E1N + e0 + 2];
    int dd2 = ei[E1N + e0 + 4];
    int dd3 = ei[E1N + e0 + 6];

    float4 v0 = ((const float4*)(d_yl + s0 * 64))[j];
    float4 v1 = ((const float4*)(d_yl + s1 * 64))[j];
    float4 v2 = ((const float4*)(d_yl + s2 * 64))[j];
    float4 v3 = ((const float4*)(d_yl + s3 * 64))[j];

    float* p0 = d_agg1 + dd0 * 64 + 4 * j;
    float* p1 = d_agg1 + dd1 * 64 + 4 * j;
    float* p2 = d_agg1 + dd2 * 64 + 4 * j;
    float* p3 = d_agg1 + dd3 * 64 + 4 * j;
    asm volatile("red.global.add.v4.f32 [%0], {%1,%2,%3,%4};"
                 :: "l"(p0), "f"(v0.x), "f"(v0.y), "f"(v0.z), "f"(v0.w) : "memory");
    asm volatile("red.global.add.v4.f32 [%0], {%1,%2,%3,%4};"
                 :: "l"(p1), "f"(v1.x), "f"(v1.y), "f"(v1.z), "f"(v1.w) : "memory");
    asm volatile("red.global.add.v4.f32 [%0], {%1,%2,%3,%4};"
                 :: "l"(p2), "f"(v2.x), "f"(v2.y), "f"(v2.z), "f"(v2.w) : "memory");
    asm volatile("red.global.add.v4.f32 [%0], {%1,%2,%3,%4};"
                 :: "l"(p3), "f"(v3.x), "f"(v3.y), "f"(v3.z), "f"(v3.w) : "memory");
    if (j == 0) {
        atomicAdd(&d_deg1[dd0], 1.0f);
        atomicAdd(&d_deg1[dd1], 1.0f);
        atomicAdd(&d_deg1[dd2], 1.0f);
        atomicAdd(&d_deg1[dd3], 1.0f);
    }
}

// ---------------- slot assignment + bitmap --------------------------------------
__global__ void slot_kernel(const int* __restrict__ targets,
                            const int* __restrict__ regions) {
    int idx = blockIdx.x * blockDim.x + threadIdx.x;
    if (idx >= BGRAPH * (AREG + 1)) return;
    int b = idx / (AREG + 1);
    int j = idx % (AREG + 1);
    int node = (j == AREG) ? targets[b] : regions[b * AREG + j];
    atomicOr(&d_bitmap[b * BMWORDS + (node >> 5)], 1u << (node & 31));
    int* p = &d_slotmap[b * NNODES + node];
    if (atomicCAS(p, -1, -2) == -1) {
        int s = atomicAdd(&d_counter[b], 1);
        atomicExch(p, s);
    }
}

// ---------------- conv2 scatter with smem bitmap filter -------------------------
__global__ void scatter2_kernel(const int* __restrict__ ne) {
    __shared__ unsigned sbm[BMWORDS];
    const int b = blockIdx.y;
    for (int i = threadIdx.x; i < BMWORDS; i += 320)
        sbm[i] = d_bitmap[b * BMWORDS + i];
    __syncthreads();

    const int lane = threadIdx.x & 31;
    const long base = (long)b * 2 * E2N;
    int e0 = blockIdx.x * 1600 + threadIdx.x;
#pragma unroll
    for (int it = 0; it < 5; it++) {
        int e = e0 + it * 320;
        int dst = ne[base + E2N + e];
        bool hit = (sbm[dst >> 5] >> (dst & 31)) & 1u;
        int slot = -1, src = 0;
        if (hit) {
            slot = d_slotmap[b * NNODES + dst];
            src = ne[base + e];
        }
        unsigned mask = __ballot_sync(0xffffffffu, hit);
        while (mask) {
            int bit = __ffs(mask) - 1;
            mask &= mask - 1;
            int es = __shfl_sync(0xffffffffu, src, bit);
            int sl = __shfl_sync(0xffffffffu, slot, bit);
            float2 v = ((const float2*)(d_gl + es * 64))[lane];
            float* p = d_acc2 + (b * SLOTS + sl) * 64 + 2 * lane;
            asm volatile("red.global.add.v2.f32 [%0], {%1,%2};"
                         :: "l"(p), "f"(v.x), "f"(v.y) : "memory");
            if (lane == 0) atomicAdd(&d_deg2[b * SLOTS + sl], 1.0f);
        }
    }
}

// ---------------- u_b = Wo @ t_b , c_b = bo . t_b -------------------------------
__global__ void u_kernel(const int* __restrict__ targets,
                         const float* __restrict__ Wo,
                         const float* __restrict__ bo) {
    int idx = blockIdx.x * blockDim.x + threadIdx.x;
    if (idx >= BGRAPH * HDIM) return;
    int b = idx >> 7;
    int h = idx & 127;
    int node = targets[b];
    int s = d_slotmap[b * NNODES + node];
    int base = (b * SLOTS + s) * 64;
    float inv = 1.f / fmaxf(d_deg2[b * SLOTS + s], 1.f);
    float acc = 0.f, c = 0.f;
#pragma unroll
    for (int d = 0; d < 64; d++) {
        float td = fmaxf(d_acc2[base + d] * inv + d_gr[node * 64 + d], 0.f);
        acc += Wo[h * 64 + d] * td;
        c += bo[d] * td;
    }
    d_u[idx] = acc;
    if (h == 0) d_c[b] = c;
}

// ---------------- final readout -------------------------------------------------
__global__ void final_kernel(const int* __restrict__ regions,
                             const float* __restrict__ Wm,
                             const float* __restrict__ bm,
                             float* __restrict__ q) {
    __shared__ float sWm[64 * 128];
    __shared__ float sreg[8][8][64];
    for (int i = threadIdx.x; i < 64 * 128; i += blockDim.x)
        sWm[i] = Wm[i];
    __syncthreads();

    const int lane = threadIdx.x & 31;
    const int wl = threadIdx.x >> 5;
    const float2 bmp0 = ((const float2*)bm)[lane];
    const float2 bmp1 = ((const float2*)bm)[lane + 32];

    for (int tile = blockIdx.x * 8 + wl; tile < 4000; tile += gridDim.x * 8) {
        int b = tile / 250;
#pragma unroll
        for (int r = 0; r < 8; r++) {
            int p = tile * 8 + r;
            int node = regions[p];
            int s = d_slotmap[b * NNODES + node];
            int base = (b * SLOTS + s) * 64;
            float inv = 1.f / fmaxf(d_deg2[b * SLOTS + s], 1.f);
            float2 a = ((const float2*)(d_acc2 + base))[lane];
            float2 g = ((const float2*)(d_gr + node * 64))[lane];
            sreg[wl][r][2 * lane]     = fmaxf(a.x * inv + g.x, 0.f);
            sreg[wl][r][2 * lane + 1] = fmaxf(a.y * inv + g.y, 0.f);
        }
        __syncwarp();

        ull acc0[8], acc1[8];
#pragma unroll
        for (int r = 0; r < 8; r++) { acc0[r] = 0ull; acc1[r] = 0ull; }

#pragma unroll 8
        for (int d = 0; d < 64; d++) {
            ull w0 = ((const ull*)(sWm + d * 128))[lane];
            ull w1 = ((const ull*)(sWm + d * 128 + 64))[lane];
#pragma unroll
            for (int r = 0; r < 8; r++) {
                float rd = sreg[wl][r][d];
                ull rdp = pack2(rd, rd);
                acc0[r] = ffma2(rdp, w0, acc0[r]);
                acc1[r] = ffma2(rdp, w1, acc1[r]);
            }
        }

        const float2* ubp = (const float2*)(d_u + b * HDIM);
        float2 u0 = ubp[lane];
        float2 u1 = ubp[lane + 32];
        float cb = d_c[b];
#pragma unroll
        for (int r = 0; r < 8; r++) {
            float m0, m1, m2, m3;
            unpack2(acc0[r], m0, m1);
            unpack2(acc1[r], m2, m3);
            float sum = fmaxf(m0 + bmp0.x, 0.f) * u0.x
                      + fmaxf(m1 + bmp0.y, 0.f) * u0.y
                      + fmaxf(m2 + bmp1.x, 0.f) * u1.x
                      + fmaxf(m3 + bmp1.y, 0.f) * u1.y;
#pragma unroll
            for (int o = 16; o > 0; o >>= 1)
                sum += __shfl_down_sync(0xffffffffu, sum, o);
            if (lane == 0) q[tile * 8 + r] = sum + cb;
        }
        __syncwarp();
    }
}

// ---------------- launch ---------------------------------------------------------
extern "C" void kernel_launch(void* const* d_in, const int* in_sizes, int n_in,
                              void* d_out, int out_size) {
    const float* x       = (const float*)d_in[0];
    const int*   ei      = (const int*)  d_in[1];
    const int*   ne      = (const int*)  d_in[2];
    const int*   targets = (const int*)  d_in[3];
    const int*   regions = (const int*)  d_in[4];
    const float* W1l     = (const float*)d_in[5];
    const float* W1r     = (const float*)d_in[6];
    const float* b1      = (const float*)d_in[7];
    const float* W2l     = (const float*)d_in[8];
    const float* W2r     = (const float*)d_in[9];
    const float* b2      = (const float*)d_in[10];
    const float* Wm      = (const float*)d_in[11];
    const float* bm      = (const float*)d_in[12];
    const float* Wo      = (const float*)d_in[13];
    const float* bo      = (const float*)d_in[14];
    float* q = (float*)d_out;

    float *p_yl, *p_yr, *p_gl, *p_gr;
    cudaGetSymbolAddress((void**)&p_yl, d_yl);
    cudaGetSymbolAddress((void**)&p_yr, d_yr);
    cudaGetSymbolAddress((void**)&p_gl, d_gl);
    cudaGetSymbolAddress((void**)&p_gr, d_gr);

    const int gemm_blocks = (NNODES + 63) / 64;   // 782

    // 0. yl = x@W1l ; yr = x@W1r + b1 (HMMA, K=128)
    mma_dual_gemm<FIN, false><<<gemm_blocks, 256>>>(x, W1l, W1r, b1, p_yl, p_yr, NNODES);

    // 1. clear scratch
    clear_kernel<<<(CLR_TOTAL + 255) / 256, 256>>>();

    // 2. conv1 scatter
    {
        int warps = E1N / 8;
        int blocks = (warps * 32 + 255) / 256;
        scatter1_kernel<<<blocks, 256>>>(ei);
    }

    // 3. gl = h1@W2l ; gr = h1@W2r + b2 (HMMA, K=64, h1 fused)  <-- profiled slot
    mma_dual_gemm<DDIM, true><<<gemm_blocks, 256>>>(nullptr, W2l, W2r, b2, p_gl, p_gr, NNODES);

    // 4. slot assignment + bitmap
    slot_kernel<<<(BGRAPH * (AREG + 1) + 255) / 256, 256>>>(targets, regions);

    // 5. conv2 scatter with smem bitmap filter
    {
        dim3 grid(125, BGRAPH);
        scatter2_kernel<<<grid, 320>>>(ne);
    }

    // 6. u_b = Wo @ t_b, c_b
    u_kernel<<<(BGRAPH * HDIM + 255) / 256, 256>>>(targets, Wo, bo);

    // 7. readout
    final_kernel<<<250, 256>>>(regions, Wm, bm, q);
}

// round 10
// speedup vs baseline: 1.0436x; 1.0436x over previous
#include <cuda_runtime.h>
#include <cuda_bf16.h>

#define NNODES 50000
#define FIN    128
#define DDIM   64
#define HDIM   128
#define BGRAPH 16
#define E1N    800000
#define E2N    200000
#define AREG   2000
#define SLOTS  2048
#define BMWORDS 1568

typedef unsigned long long ull;
typedef unsigned int u32;

// ---------------- f32x2 / bf16 helpers ------------------------------------------
__device__ __forceinline__ ull ffma2(ull a, ull b, ull c) {
    ull d;
    asm("fma.rn.f32x2 %0, %1, %2, %3;" : "=l"(d) : "l"(a), "l"(b), "l"(c));
    return d;
}
__device__ __forceinline__ ull pack2(float lo, float hi) {
    ull r;
    asm("mov.b64 %0, {%1, %2};" : "=l"(r) : "f"(lo), "f"(hi));
    return r;
}
__device__ __forceinline__ void unpack2(ull v, float& lo, float& hi) {
    asm("mov.b64 {%0, %1}, %2;" : "=f"(lo), "=f"(hi) : "l"(v));
}
__device__ __forceinline__ u32 bf2_hi(float a, float b) {
    __nv_bfloat162 h = __floats2bfloat162_rn(a, b);
    return *reinterpret_cast<u32*>(&h);
}
__device__ __forceinline__ u32 bf2_lo(float a, float b) {
    float ra = a - __bfloat162float(__float2bfloat16(a));
    float rb = b - __bfloat162float(__float2bfloat16(b));
    __nv_bfloat162 l = __floats2bfloat162_rn(ra, rb);
    return *reinterpret_cast<u32*>(&l);
}
__device__ __forceinline__ void mma16816(float* c, u32 a0, u32 a1, u32 a2, u32 a3,
                                         u32 b0, u32 b1) {
    asm("mma.sync.aligned.m16n8k16.row.col.f32.bf16.bf16.f32 "
        "{%0,%1,%2,%3}, {%4,%5,%6,%7}, {%8,%9}, {%0,%1,%2,%3};"
        : "+f"(c[0]), "+f"(c[1]), "+f"(c[2]), "+f"(c[3])
        : "r"(a0), "r"(a1), "r"(a2), "r"(a3), "r"(b0), "r"(b1));
}

// ---------------- scratch -------------------------------------------------------
__device__ __align__(16) float d_yl[NNODES * DDIM];
__device__ __align__(16) float d_yr[NNODES * DDIM];
__device__ __align__(16) float d_agg1[NNODES * DDIM];
__device__ __align__(16) float d_deg1[NNODES];
__device__ __align__(16) float d_gl[NNODES * DDIM];
__device__ __align__(16) float d_gr[NNODES * DDIM];
__device__ __align__(16) int   d_slotmap[BGRAPH * NNODES];
__device__ __align__(16) unsigned d_bitmap[BGRAPH * BMWORDS];
__device__ __align__(16) int   d_counter[BGRAPH];
__device__ __align__(16) float d_acc2[BGRAPH * SLOTS * DDIM];
__device__ __align__(16) float d_deg2[BGRAPH * SLOTS];
__device__ __align__(16) float d_u[BGRAPH * HDIM];
__device__ __align__(16) float d_c[BGRAPH];

// ---------------- clear kernel --------------------------------------------------
static constexpr int CLR_AGG1 = NNODES * DDIM / 4;
static constexpr int CLR_ACC2 = BGRAPH * SLOTS * DDIM / 4;
static constexpr int CLR_SMAP = BGRAPH * NNODES / 4;
static constexpr int CLR_BMAP = BGRAPH * BMWORDS / 4;
static constexpr int CLR_DEG1 = NNODES / 4;
static constexpr int CLR_DEG2 = BGRAPH * SLOTS / 4;
static constexpr int CLR_CNT  = BGRAPH / 4;
static constexpr int CLR_TOTAL = CLR_AGG1 + CLR_ACC2 + CLR_SMAP + CLR_BMAP +
                                 CLR_DEG1 + CLR_DEG2 + CLR_CNT;

__global__ void clear_kernel() {
    int i = blockIdx.x * blockDim.x + threadIdx.x;
    float4 z = make_float4(0.f, 0.f, 0.f, 0.f);
    if (i < CLR_AGG1) { ((float4*)d_agg1)[i] = z; return; }
    i -= CLR_AGG1;
    if (i < CLR_ACC2) { ((float4*)d_acc2)[i] = z; return; }
    i -= CLR_ACC2;
    if (i < CLR_SMAP) { ((int4*)d_slotmap)[i] = make_int4(-1, -1, -1, -1); return; }
    i -= CLR_SMAP;
    if (i < CLR_BMAP) { ((uint4*)d_bitmap)[i] = make_uint4(0, 0, 0, 0); return; }
    i -= CLR_BMAP;
    if (i < CLR_DEG1) { ((float4*)d_deg1)[i] = z; return; }
    i -= CLR_DEG1;
    if (i < CLR_DEG2) { ((float4*)d_deg2)[i] = z; return; }
    i -= CLR_DEG2;
    if (i < CLR_CNT)  { ((int4*)d_counter)[i] = make_int4(0, 0, 0, 0); }
}

// ================= HMMA bf16-split dual GEMM (128-row CTA, fragment-shared) =====
// Per CTA: D[128, 128] = A[128, K] @ [W1 | W2]; cols 0..63 -> C1, 64..127 -> C2+bias.
// bf16 split: D = Ah·Bh + Al·Bh + Ah·Bl (ll dropped, ~1.5e-5 rel).
// Inner loop loads each smem fragment ONCE: Bh reused for Ah & Al terms.
template <int K, bool FUSE_H1>
__global__ __launch_bounds__(256) void mma_dual_gemm(const float* __restrict__ A,
                                                     const float* __restrict__ W1,
                                                     const float* __restrict__ W2,
                                                     const float* __restrict__ bias,
                                                     float* __restrict__ C1,
                                                     float* __restrict__ C2,
                                                     int nrows) {
    __shared__ __align__(16) __nv_bfloat16 sAh[128 * 48];
    __shared__ __align__(16) __nv_bfloat16 sAl[128 * 48];
    __shared__ __align__(16) __nv_bfloat16 sBh[128 * 48];
    __shared__ __align__(16) __nv_bfloat16 sBl[128 * 48];

    const int t = threadIdx.x;
    const int w = t >> 5, lane = t & 31;
    const int g = lane >> 2, tg = lane & 3;
    const int row0 = blockIdx.x * 128;

    float acc[16][4];
#pragma unroll
    for (int nt = 0; nt < 16; nt++)
#pragma unroll
        for (int i = 0; i < 4; i++) acc[nt][i] = 0.f;

    for (int k0 = 0; k0 < K; k0 += 32) {
        // ---- fill A chunk (rows row0..row0+127, k k0..k0+31), hi+lo ----
        {
            int r = t >> 1, half = t & 1;
            int row = row0 + r;
            float inv = 1.f;
            if (FUSE_H1 && row < nrows) inv = 1.f / fmaxf(d_deg1[row], 1.f);
#pragma unroll
            for (int j = 0; j < 8; j++) {
                int jg = half * 8 + j;
                int k = 2 * jg;
                float2 v = make_float2(0.f, 0.f);
                if (row < nrows) {
                    if (FUSE_H1) {
                        float2 ag = *(const float2*)(d_agg1 + row * 64 + k0 + k);
                        float2 yv = *(const float2*)(d_yr + row * 64 + k0 + k);
                        v.x = fmaxf(ag.x * inv + yv.x, 0.f);
                        v.y = fmaxf(ag.y * inv + yv.y, 0.f);
                    } else {
                        v = *(const float2*)(A + (long)row * K + k0 + k);
                    }
                }
                int pp = ((jg >> 2) & 1) + (jg & 3) * 2 + (jg >> 3) * 8;
                ((u32*)(sAh + r * 48))[pp] = bf2_hi(v.x, v.y);
                ((u32*)(sAl + r * 48))[pp] = bf2_lo(v.x, v.y);
            }
        }
        // ---- fill B chunk: n 0..127 = [W1 col | W2 col], k k0..k0+31 ----
        {
            int n = t >> 1, half = t & 1;
            const float* W = (n < 64) ? W1 : W2;
            int nc = (n < 64) ? n : n - 64;
#pragma unroll
            for (int j = 0; j < 8; j++) {
                int jg = half * 8 + j;
                int k = k0 + 2 * jg;
                float wx = W[k * 64 + nc];
                float wy = W[(k + 1) * 64 + nc];
                int pp = ((jg >> 2) & 1) + (jg & 3) * 2 + (jg >> 3) * 8;
                ((u32*)(sBh + n * 48))[pp] = bf2_hi(wx, wy);
                ((u32*)(sBl + n * 48))[pp] = bf2_lo(wx, wy);
            }
        }
        __syncthreads();

        // ---- fragment-shared mainloop: 2 k16 steps x 16 n-tiles x 3 MMAs ----
#pragma unroll
        for (int ks = 0; ks < 2; ks++) {
            ull ah0 = *(const ull*)(sAh + (w * 16 + g) * 48 + ks * 16 + tg * 4);
            ull ah1 = *(const ull*)(sAh + (w * 16 + g + 8) * 48 + ks * 16 + tg * 4);
            ull al0 = *(const ull*)(sAl + (w * 16 + g) * 48 + ks * 16 + tg * 4);
            ull al1 = *(const ull*)(sAl + (w * 16 + g + 8) * 48 + ks * 16 + tg * 4);
            u32 h0 = (u32)ah0, h2 = (u32)(ah0 >> 32);
            u32 h1 = (u32)ah1, h3 = (u32)(ah1 >> 32);
            u32 l0 = (u32)al0, l2 = (u32)(al0 >> 32);
            u32 l1 = (u32)al1, l3 = (u32)(al1 >> 32);
#pragma unroll
            for (int nt = 0; nt < 16; nt++) {
                ull bh = *(const ull*)(sBh + (nt * 8 + g) * 48 + ks * 16 + tg * 4);
                u32 bh0 = (u32)bh, bh1 = (u32)(bh >> 32);
                mma16816(acc[nt], h0, h1, h2, h3, bh0, bh1);
                mma16816(acc[nt], l0, l1, l2, l3, bh0, bh1);
                ull bl = *(const ull*)(sBl + (nt * 8 + g) * 48 + ks * 16 + tg * 4);
                mma16816(acc[nt], h0, h1, h2, h3, (u32)bl, (u32)(bl >> 32));
            }
        }
        __syncthreads();
    }

    // ---- store: c0/c1 -> row, c2/c3 -> row+8; col = nt*8 + tg*2 ----
    int r0 = row0 + w * 16 + g;
#pragma unroll
    for (int nt = 0; nt < 16; nt++) {
        int col = nt * 8 + tg * 2;
        if (col < 64) {
            if (r0 < nrows)
                *(float2*)(C1 + (long)r0 * 64 + col) = make_float2(acc[nt][0], acc[nt][1]);
            if (r0 + 8 < nrows)
                *(float2*)(C1 + (long)(r0 + 8) * 64 + col) = make_float2(acc[nt][2], acc[nt][3]);
        } else {
            int c2 = col - 64;
            float2 bb = *(const float2*)(bias + c2);
            if (r0 < nrows)
                *(float2*)(C2 + (long)r0 * 64 + c2) =
                    make_float2(acc[nt][0] + bb.x, acc[nt][1] + bb.y);
            if (r0 + 8 < nrows)
                *(float2*)(C2 + (long)(r0 + 8) * 64 + c2) =
                    make_float2(acc[nt][2] + bb.x, acc[nt][3] + bb.y);
        }
    }
}

// ---------------- conv1 edge scatter (8 edges/warp) -----------------------------
__global__ void scatter1_kernel(const int* __restrict__ ei) {
    int tid = blockIdx.x * blockDim.x + threadIdx.x;
    int w = tid >> 5, lane = tid & 31;
    int e0 = 8 * w + (lane >> 4);
    int j = lane & 15;

    int s0 = ei[e0];
    int s1 = ei[e0 + 2];
    int s2 = ei[e0 + 4];
    int s3 = ei[e0 + 6];
    int dd0 = ei[E1N + e0];
    int dd1 = ei[E1N + e0 + 2];
    int dd2 = ei[E1N + e0 + 4];
    int dd3 = ei[E1N + e0 + 6];

    float4 v0 = ((const float4*)(d_yl + s0 * 64))[j];
    float4 v1 = ((const float4*)(d_yl + s1 * 64))[j];
    float4 v2 = ((const float4*)(d_yl + s2 * 64))[j];
    float4 v3 = ((const float4*)(d_yl + s3 * 64))[j];

    float* p0 = d_agg1 + dd0 * 64 + 4 * j;
    float* p1 = d_agg1 + dd1 * 64 + 4 * j;
    float* p2 = d_agg1 + dd2 * 64 + 4 * j;
    float* p3 = d_agg1 + dd3 * 64 + 4 * j;
    asm volatile("red.global.add.v4.f32 [%0], {%1,%2,%3,%4};"
                 :: "l"(p0), "f"(v0.x), "f"(v0.y), "f"(v0.z), "f"(v0.w) : "memory");
    asm volatile("red.global.add.v4.f32 [%0], {%1,%2,%3,%4};"
                 :: "l"(p1), "f"(v1.x), "f"(v1.y), "f"(v1.z), "f"(v1.w) : "memory");
    asm volatile("red.global.add.v4.f32 [%0], {%1,%2,%3,%4};"
                 :: "l"(p2), "f"(v2.x), "f"(v2.y), "f"(v2.z), "f"(v2.w) : "memory");
    asm volatile("red.global.add.v4.f32 [%0], {%1,%2,%3,%4};"
                 :: "l"(p3), "f"(v3.x), "f"(v3.y), "f"(v3.z), "f"(v3.w) : "memory");
    if (j == 0) {
        atomicAdd(&d_deg1[dd0], 1.0f);
        atomicAdd(&d_deg1[dd1], 1.0f);
        atomicAdd(&d_deg1[dd2], 1.0f);
        atomicAdd(&d_deg1[dd3], 1.0f);
    }
}

// ---------------- slot assignment + bitmap --------------------------------------
__global__ void slot_kernel(const int* __restrict__ targets,
                            const int* __restrict__ regions) {
    int idx = blockIdx.x * blockDim.x + threadIdx.x;
    if (idx >= BGRAPH * (AREG + 1)) return;
    int b = idx / (AREG + 1);
    int j = idx % (AREG + 1);
    int node = (j == AREG) ? targets[b] : regions[b * AREG + j];
    atomicOr(&d_bitmap[b * BMWORDS + (node >> 5)], 1u << (node & 31));
    int* p = &d_slotmap[b * NNODES + node];
    if (atomicCAS(p, -1, -2) == -1) {
        int s = atomicAdd(&d_counter[b], 1);
        atomicExch(p, s);
    }
}

// ---------------- conv2 scatter with smem bitmap filter -------------------------
__global__ void scatter2_kernel(const int* __restrict__ ne) {
    __shared__ unsigned sbm[BMWORDS];
    const int b = blockIdx.y;
    for (int i = threadIdx.x; i < BMWORDS; i += 320)
        sbm[i] = d_bitmap[b * BMWORDS + i];
    __syncthreads();

    const int lane = threadIdx.x & 31;
    const long base = (long)b * 2 * E2N;
    int e0 = blockIdx.x * 1600 + threadIdx.x;
#pragma unroll
    for (int it = 0; it < 5; it++) {
        int e = e0 + it * 320;
        int dst = ne[base + E2N + e];
        bool hit = (sbm[dst >> 5] >> (dst & 31)) & 1u;
        int slot = -1, src = 0;
        if (hit) {
            slot = d_slotmap[b * NNODES + dst];
            src = ne[base + e];
        }
        unsigned mask = __ballot_sync(0xffffffffu, hit);
        while (mask) {
            int bit = __ffs(mask) - 1;
            mask &= mask - 1;
            int es = __shfl_sync(0xffffffffu, src, bit);
            int sl = __shfl_sync(0xffffffffu, slot, bit);
            float2 v = ((const float2*)(d_gl + es * 64))[lane];
            float* p = d_acc2 + (b * SLOTS + sl) * 64 + 2 * lane;
            asm volatile("red.global.add.v2.f32 [%0], {%1,%2};"
                         :: "l"(p), "f"(v.x), "f"(v.y) : "memory");
            if (lane == 0) atomicAdd(&d_deg2[b * SLOTS + sl], 1.0f);
        }
    }
}

// ---------------- u_b = Wo @ t_b , c_b = bo . t_b -------------------------------
__global__ void u_kernel(const int* __restrict__ targets,
                         const float* __restrict__ Wo,
                         const float* __restrict__ bo) {
    int idx = blockIdx.x * blockDim.x + threadIdx.x;
    if (idx >= BGRAPH * HDIM) return;
    int b = idx >> 7;
    int h = idx & 127;
    int node = targets[b];
    int s = d_slotmap[b * NNODES + node];
    int base = (b * SLOTS + s) * 64;
    float inv = 1.f / fmaxf(d_deg2[b * SLOTS + s], 1.f);
    float acc = 0.f, c = 0.f;
#pragma unroll
    for (int d = 0; d < 64; d++) {
        float td = fmaxf(d_acc2[base + d] * inv + d_gr[node * 64 + d], 0.f);
        acc += Wo[h * 64 + d] * td;
        c += bo[d] * td;
    }
    d_u[idx] = acc;
    if (h == 0) d_c[b] = c;
}

// ---------------- final readout -------------------------------------------------
__global__ void final_kernel(const int* __restrict__ regions,
                             const float* __restrict__ Wm,
                             const float* __restrict__ bm,
                             float* __restrict__ q) {
    __shared__ float sWm[64 * 128];
    __shared__ float sreg[8][8][64];
    for (int i = threadIdx.x; i < 64 * 128; i += blockDim.x)
        sWm[i] = Wm[i];
    __syncthreads();

    const int lane = threadIdx.x & 31;
    const int wl = threadIdx.x >> 5;
    const float2 bmp0 = ((const float2*)bm)[lane];
    const float2 bmp1 = ((const float2*)bm)[lane + 32];

    for (int tile = blockIdx.x * 8 + wl; tile < 4000; tile += gridDim.x * 8) {
        int b = tile / 250;
#pragma unroll
        for (int r = 0; r < 8; r++) {
            int p = tile * 8 + r;
            int node = regions[p];
            int s = d_slotmap[b * NNODES + node];
            int base = (b * SLOTS + s) * 64;
            float inv = 1.f / fmaxf(d_deg2[b * SLOTS + s], 1.f);
            float2 a = ((const float2*)(d_acc2 + base))[lane];
            float2 g = ((const float2*)(d_gr + node * 64))[lane];
            sreg[wl][r][2 * lane]     = fmaxf(a.x * inv + g.x, 0.f);
            sreg[wl][r][2 * lane + 1] = fmaxf(a.y * inv + g.y, 0.f);
        }
        __syncwarp();

        ull acc0[8], acc1[8];
#pragma unroll
        for (int r = 0; r < 8; r++) { acc0[r] = 0ull; acc1[r] = 0ull; }

#pragma unroll 8
        for (int d = 0; d < 64; d++) {
            ull w0 = ((const ull*)(sWm + d * 128))[lane];
            ull w1 = ((const ull*)(sWm + d * 128 + 64))[lane];
#pragma unroll
            for (int r = 0; r < 8; r++) {
                float rd = sreg[wl][r][d];
                ull rdp = pack2(rd, rd);
                acc0[r] = ffma2(rdp, w0, acc0[r]);
                acc1[r] = ffma2(rdp, w1, acc1[r]);
            }
        }

        const float2* ubp = (const float2*)(d_u + b * HDIM);
        float2 u0 = ubp[lane];
        float2 u1 = ubp[lane + 32];
        float cb = d_c[b];
#pragma unroll
        for (int r = 0; r < 8; r++) {
            float m0, m1, m2, m3;
            unpack2(acc0[r], m0, m1);
            unpack2(acc1[r], m2, m3);
            float sum = fmaxf(m0 + bmp0.x, 0.f) * u0.x
                      + fmaxf(m1 + bmp0.y, 0.f) * u0.y
                      + fmaxf(m2 + bmp1.x, 0.f) * u1.x
                      + fmaxf(m3 + bmp1.y, 0.f) * u1.y;
#pragma unroll
            for (int o = 16; o > 0; o >>= 1)
                sum += __shfl_down_sync(0xffffffffu, sum, o);
            if (lane == 0) q[tile * 8 + r] = sum + cb;
        }
        __syncwarp();
    }
}

// ---------------- launch ---------------------------------------------------------
extern "C" void kernel_launch(void* const* d_in, const int* in_sizes, int n_in,
                              void* d_out, int out_size) {
    const float* x       = (const float*)d_in[0];
    const int*   ei      = (const int*)  d_in[1];
    const int*   ne      = (const int*)  d_in[2];
    const int*   targets = (const int*)  d_in[3];
    const int*   regions = (const int*)  d_in[4];
    const float* W1l     = (const float*)d_in[5];
    const float* W1r     = (const float*)d_in[6];
    const float* b1      = (const float*)d_in[7];
    const float* W2l     = (const float*)d_in[8];
    const float* W2r     = (const float*)d_in[9];
    const float* b2      = (const float*)d_in[10];
    const float* Wm      = (const float*)d_in[11];
    const float* bm      = (const float*)d_in[12];
    const float* Wo      = (const float*)d_in[13];
    const float* bo      = (const float*)d_in[14];
    float* q = (float*)d_out;

    float *p_yl, *p_yr, *p_gl, *p_gr;
    cudaGetSymbolAddress((void**)&p_yl, d_yl);
    cudaGetSymbolAddress((void**)&p_yr, d_yr);
    cudaGetSymbolAddress((void**)&p_gl, d_gl);
    cudaGetSymbolAddress((void**)&p_gr, d_gr);

    const int gemm_blocks = (NNODES + 127) / 128;   // 391

    // 0. yl = x@W1l ; yr = x@W1r + b1 (HMMA, K=128)
    mma_dual_gemm<FIN, false><<<gemm_blocks, 256>>>(x, W1l, W1r, b1, p_yl, p_yr, NNODES);

    // 1. clear scratch
    clear_kernel<<<(CLR_TOTAL + 255) / 256, 256>>>();

    // 2. conv1 scatter
    {
        int warps = E1N / 8;
        int blocks = (warps * 32 + 255) / 256;
        scatter1_kernel<<<blocks, 256>>>(ei);
    }

    // 3. gl = h1@W2l ; gr = h1@W2r + b2 (HMMA, K=64, h1 fused)  <-- profiled slot
    mma_dual_gemm<DDIM, true><<<gemm_blocks, 256>>>(nullptr, W2l, W2r, b2, p_gl, p_gr, NNODES);

    // 4. slot assignment + bitmap
    slot_kernel<<<(BGRAPH * (AREG + 1) + 255) / 256, 256>>>(targets, regions);

    // 5. conv2 scatter with smem bitmap filter
    {
        dim3 grid(125, BGRAPH);
        scatter2_kernel<<<grid, 320>>>(ne);
    }

    // 6. u_b = Wo @ t_b, c_b
    u_kernel<<<(BGRAPH * HDIM + 255) / 256, 256>>>(targets, Wo, bo);

    // 7. readout
    final_kernel<<<250, 256>>>(regions, Wm, bm, q);
}